// round 12
// baseline (speedup 1.0000x reference)
#include <cuda_runtime.h>
#include <cuda_bf16.h>
#include <cuda_fp16.h>
#include <cstdint>

#define N_NODES 50000
#define N_EDGES 600000
#define D 128

// ---------------------------------------------------------------------------
// Scratch (__device__ globals; zero-initialized at module load)
// ---------------------------------------------------------------------------
__device__ __half g_h16[(size_t)N_NODES * D]; // h~ = fp16(h * dis[src])
__device__ float  g_dis[N_NODES];             // rsqrt(deg+1)
__device__ int    g_deg[N_NODES];             // in-degree counts (reset by gemm)
__device__ int    g_idx_is32;                 // 1 if edge_index is int32
__device__ int    g_esrc[N_EDGES];            // CSR: src ids grouped by dst
__device__ int    g_rowstart[N_NODES + 1];    // CSR row offsets
__device__ int    g_cursor[N_NODES];          // fill cursors (rebuilt per replay)

// ---------------------------------------------------------------------------
// Index dtype handling
// ---------------------------------------------------------------------------
__device__ __forceinline__ int probe_is32(const void* ei) {
    const long long* p = (const long long*)ei;
    int is32 = 0;
#pragma unroll
    for (int i = 0; i < 4; i++) {
        long long v = p[i];
        if (v < 0 || v >= N_NODES) is32 = 1;
    }
    return is32;
}
__device__ __forceinline__ int load_idx(const void* ei, long long i, int is32) {
    if (is32) return ((const int*)ei)[i];
    return (int)((const long long*)ei)[i];
}

// ---------------------------------------------------------------------------
// K1: degree count, 2 edges per thread (+ publish index dtype)
// ---------------------------------------------------------------------------
__global__ void deg_count_kernel(const void* __restrict__ ei) {
    int e0 = (blockIdx.x * blockDim.x + threadIdx.x) * 2;
    int is32 = probe_is32(ei);
    if (e0 == 0) g_idx_is32 = is32;
#pragma unroll
    for (int j = 0; j < 2; j++) {
        int e = e0 + j;
        if (e < N_EDGES) {
            int d = load_idx(ei, (long long)N_EDGES + e, is32);
            atomicAdd(&g_deg[d], 1);
        }
    }
}

// ---------------------------------------------------------------------------
// K2: fused exclusive scan (single block, 1024 threads, int4 chunks of 4096).
// g_deg -> g_rowstart[0..N], g_cursor.  N_NODES % 4 == 0.
// ---------------------------------------------------------------------------
#define SCHUNK 4096
#define NCHUNK ((N_NODES + SCHUNK - 1) / SCHUNK)   // 13

__global__ void __launch_bounds__(1024)
scan_kernel() {
    __shared__ int ws[32];
    __shared__ int s_carry;
    const int t = threadIdx.x, lane = t & 31, w = t >> 5;
    if (t == 0) s_carry = 0;
    __syncthreads();

    for (int c = 0; c < NCHUNK; c++) {
        int i4 = c * SCHUNK + t * 4;
        int4 v = make_int4(0, 0, 0, 0);
        if (i4 < N_NODES) v = *(const int4*)(g_deg + i4);
        int tsum = v.x + v.y + v.z + v.w;

        // warp inclusive scan of per-thread sums
        int x = tsum;
#pragma unroll
        for (int o = 1; o < 32; o <<= 1) {
            int y = __shfl_up_sync(0xffffffffu, x, o);
            if (lane >= o) x += y;
        }
        if (lane == 31) ws[w] = x;
        __syncthreads();
        if (w == 0) {                        // scan the 32 warp totals
            int z = ws[lane];
#pragma unroll
            for (int o = 1; o < 32; o <<= 1) {
                int y = __shfl_up_sync(0xffffffffu, z, o);
                if (lane >= o) z += y;
            }
            ws[lane] = z;
        }
        __syncthreads();
        int woff = (w > 0) ? ws[w - 1] : 0;
        int e0 = s_carry + woff + (x - tsum);   // exclusive prefix of v.x
        if (i4 < N_NODES) {
            int4 o4;
            o4.x = e0;
            o4.y = e0 + v.x;
            o4.z = o4.y + v.y;
            o4.w = o4.z + v.z;
            *(int4*)(g_rowstart + i4) = o4;
            *(int4*)(g_cursor + i4)   = o4;
        }
        int btot = ws[31];
        __syncthreads();
        if (t == 0) s_carry += btot;
        __syncthreads();
    }
    if (t == 0) g_rowstart[N_NODES] = s_carry;   // = N_EDGES
}

// ---------------------------------------------------------------------------
// K3: bucket fill — group src ids by dst (order within bucket irrelevant)
// ---------------------------------------------------------------------------
__global__ void fill_kernel(const void* __restrict__ ei) {
    int e = blockIdx.x * blockDim.x + threadIdx.x;
    if (e < N_EDGES) {
        int is32 = g_idx_is32;
        int s = load_idx(ei, e, is32);
        int d = load_idx(ei, (long long)N_EDGES + e, is32);
        int pos = atomicAdd(&g_cursor[d], 1);
        g_esrc[pos] = s;
    }
}

// ---------------------------------------------------------------------------
// K4: bf16-3x tensor GEMM via mma.sync.m16n8k16 + ldmatrix.x4 operand loads.
// Stores ONLY g_h16 = fp16(h * dis[row]); out written by aggregate.
// Also finalizes g_dis = rsqrt(deg+1), resets g_deg for replay.
// SMEM rows: 128 bf16 data padded to 136 (68 words); ldmatrix row segments
// cover all 32 banks exactly once -> conflict-free.
// ---------------------------------------------------------------------------
#define APAD      136
#define APADW     68
#define TILE_B    (128 * APAD * 2)
#define SM_DIS    0
#define SM_AHI    512
#define SM_ALO    (SM_AHI + TILE_B)
#define SM_BHI    (SM_ALO + TILE_B)
#define SM_BLO    (SM_BHI + TILE_B)
#define SM_TOTAL  (SM_BLO + TILE_B)  // 139776 bytes

__device__ __forceinline__ uint32_t smem_u32(const void* p) {
    uint32_t a;
    asm("{ .reg .u64 t; cvta.to.shared.u64 t, %1; cvt.u32.u64 %0, t; }"
        : "=r"(a) : "l"(p));
    return a;
}

#define LDSM_X4(R0, R1, R2, R3, ADDR) \
    asm volatile("ldmatrix.sync.aligned.m8n8.x4.shared.b16 {%0,%1,%2,%3}, [%4];" \
        : "=r"(R0), "=r"(R1), "=r"(R2), "=r"(R3) : "r"(ADDR))

__device__ __forceinline__ void mma16816(float* c, const uint32_t* a,
                                         uint32_t b0, uint32_t b1) {
    asm volatile(
        "mma.sync.aligned.m16n8k16.row.col.f32.bf16.bf16.f32 "
        "{%0,%1,%2,%3}, {%4,%5,%6,%7}, {%8,%9}, {%0,%1,%2,%3};"
        : "+f"(c[0]), "+f"(c[1]), "+f"(c[2]), "+f"(c[3])
        : "r"(a[0]), "r"(a[1]), "r"(a[2]), "r"(a[3]), "r"(b0), "r"(b1));
}

__device__ __forceinline__ uint32_t pack_hi2(float x, float y) {
    __nv_bfloat162 t = make_bfloat162(__float2bfloat16_rn(x), __float2bfloat16_rn(y));
    return *(uint32_t*)&t;
}
__device__ __forceinline__ uint32_t pack_lo2(float x, float y) {
    float hx = __bfloat162float(__float2bfloat16_rn(x));
    float hy = __bfloat162float(__float2bfloat16_rn(y));
    __nv_bfloat162 t = make_bfloat162(__float2bfloat16_rn(x - hx),
                                      __float2bfloat16_rn(y - hy));
    return *(uint32_t*)&t;
}

__global__ void __launch_bounds__(256, 1)
gemm_kernel(const float* __restrict__ x,
            const float* __restrict__ W) {
    extern __shared__ char smem[];
    float*    ep_dis = (float*)(smem + SM_DIS);
    uint32_t* AsHi = (uint32_t*)(smem + SM_AHI);
    uint32_t* AsLo = (uint32_t*)(smem + SM_ALO);

    const int tid  = threadIdx.x;
    const int wid  = tid >> 5;
    const int lane = tid & 31;
    const int row0 = blockIdx.x * 128;

    // --- Degree finalize for this block's rows ---
    if (tid < 128) {
        int gr = row0 + tid;
        float dis = 0.0f;
        if (gr < N_NODES) {
            int deg = g_deg[gr];
            dis = rsqrtf((float)(deg + 1));
            g_dis[gr] = dis;
            g_deg[gr] = 0;           // reset for next graph replay
        }
        ep_dis[tid] = dis;
    }

    // --- A tile: x[row0..row0+128) -> hi/lo bf16 ---
    for (int i = tid; i < 128 * 32; i += 256) {
        int r  = i >> 5;
        int c4 = (i & 31) << 2;
        int gr = row0 + r;
        float4 v = make_float4(0.f, 0.f, 0.f, 0.f);
        if (gr < N_NODES) v = *(const float4*)(x + (size_t)gr * D + c4);
        uint32_t* dh = AsHi + r * APADW + (c4 >> 1);
        uint32_t* dl = AsLo + r * APADW + (c4 >> 1);
        dh[0] = pack_hi2(v.x, v.y);
        dh[1] = pack_hi2(v.z, v.w);
        dl[0] = pack_lo2(v.x, v.y);
        dl[1] = pack_lo2(v.z, v.w);
    }

    // --- B tile: W^T (n-major rows, k contiguous) hi/lo bf16 ---
    for (int i = tid; i < 128 * 64; i += 256) {
        int k  = i >> 6;
        int n2 = (i & 63) << 1;
        float2 v = *(const float2*)(W + k * D + n2);
        __nv_bfloat16* bh = (__nv_bfloat16*)(smem + SM_BHI);
        __nv_bfloat16* bl = (__nv_bfloat16*)(smem + SM_BLO);
        float h0f = __bfloat162float(__float2bfloat16_rn(v.x));
        float h1f = __bfloat162float(__float2bfloat16_rn(v.y));
        bh[(n2 + 0) * APAD + k] = __float2bfloat16_rn(v.x);
        bh[(n2 + 1) * APAD + k] = __float2bfloat16_rn(v.y);
        bl[(n2 + 0) * APAD + k] = __float2bfloat16_rn(v.x - h0f);
        bl[(n2 + 1) * APAD + k] = __float2bfloat16_rn(v.y - h1f);
    }
    __syncthreads();

    // --- MMA mainloop (ldmatrix.x4 operand loads) ---
    const int g = lane >> 2;
    const int t = lane & 3;
    const int wrow = wid * 16;
    const uint32_t sb = smem_u32(smem);
    const int r8 = lane & 7;

    // A lane address: matrices {rows+0,rows+8} x {words+0,words+4}
    const uint32_t aRow  = (uint32_t)(wrow + ((lane >> 3) & 1) * 8 + r8);
    const uint32_t aWsel = (uint32_t)((lane >> 4) * 4);
    uint32_t aHiA = sb + SM_AHI + (aRow * APADW + aWsel) * 4;
    uint32_t aLoA = sb + SM_ALO + (aRow * APADW + aWsel) * 4;

    // B lane address for nt-pair p: matrices {nt, nt} x {w0, w+4}, {nt+1,...}
    const uint32_t bRow  = (uint32_t)(((lane >> 4) & 1) * 8 + r8);
    const uint32_t bWsel = (uint32_t)(((lane >> 3) & 1) * 4);
    const uint32_t bHiA0 = sb + SM_BHI + (bRow * APADW + bWsel) * 4;
    const uint32_t bLoA0 = sb + SM_BLO + (bRow * APADW + bWsel) * 4;
    const uint32_t bStride = 16 * APADW * 4;     // 2 n-tiles of 8 rows

    float acc[16][4];
#pragma unroll
    for (int nt = 0; nt < 16; nt++)
#pragma unroll
        for (int j = 0; j < 4; j++) acc[nt][j] = 0.0f;

#pragma unroll
    for (int ks = 0; ks < 8; ks++) {
        uint32_t ahi[4], alo[4];
        LDSM_X4(ahi[0], ahi[1], ahi[2], ahi[3], aHiA + ks * 32);
        LDSM_X4(alo[0], alo[1], alo[2], alo[3], aLoA + ks * 32);
        uint32_t bh = bHiA0 + ks * 32;
        uint32_t bl = bLoA0 + ks * 32;
#pragma unroll
        for (int p = 0; p < 8; p++) {
            uint32_t b0, b1, b2, b3, c0, c1, c2, c3;
            LDSM_X4(b0, b1, b2, b3, bh);
            LDSM_X4(c0, c1, c2, c3, bl);
            mma16816(acc[2 * p],     ahi, b0, b1);
            mma16816(acc[2 * p],     ahi, c0, c1);
            mma16816(acc[2 * p],     alo, b0, b1);
            mma16816(acc[2 * p + 1], ahi, b2, b3);
            mma16816(acc[2 * p + 1], ahi, c2, c3);
            mma16816(acc[2 * p + 1], alo, b2, b3);
            bh += bStride;
            bl += bStride;
        }
    }

    // --- Epilogue: g_h16 = fp16(h * dis[row]) ---
    const int r0 = row0 + wrow + g;
    const int r1 = r0 + 8;
    const float d0 = ep_dis[wrow + g];
    const float d1 = ep_dis[wrow + g + 8];
    const bool ok0 = (r0 < N_NODES), ok1 = (r1 < N_NODES);
#pragma unroll
    for (int nt = 0; nt < 16; nt++) {
        const int c = nt * 8 + 2 * t;
        if (ok0) {
            float2 hv = make_float2(acc[nt][0] * d0, acc[nt][1] * d0);
            *(__half2*)(g_h16 + (size_t)r0 * D + c) = __float22half2_rn(hv);
        }
        if (ok1) {
            float2 hv = make_float2(acc[nt][2] * d1, acc[nt][3] * d1);
            *(__half2*)(g_h16 + (size_t)r1 * D + c) = __float22half2_rn(hv);
        }
    }
}

// ---------------------------------------------------------------------------
// K5: pull aggregation. One warp per dst node; lane l owns cols [4l, 4l+4).
// out[d] = b + dis[d] * (h~[d] + sum_{s in N(d)} h~[s])   -- no atomics.
// ---------------------------------------------------------------------------
__global__ void __launch_bounds__(256)
agg_kernel(const float* __restrict__ bias, float* __restrict__ out) {
    int node = blockIdx.x * 8 + (threadIdx.x >> 5);
    int lane = threadIdx.x & 31;
    if (node >= N_NODES) return;

    const int rs = g_rowstart[node];
    const int re = g_rowstart[node + 1];

    // self-loop seed
    uint2 u = ((const uint2*)(g_h16 + (size_t)node * D))[lane];
    float2 a0 = __half22float2(*(__half2*)&u.x);
    float2 a1 = __half22float2(*(__half2*)&u.y);
    float acc0 = a0.x, acc1 = a0.y, acc2 = a1.x, acc3 = a1.y;

    for (int base = rs; base < re; base += 32) {
        int n = re - base;                       // edges in this batch (<=32)
        int sv = (lane < n) ? g_esrc[base + lane] : 0;
#pragma unroll 4
        for (int j = 0; j < 32; j++) {
            if (j >= n) break;
            int s = __shfl_sync(0xffffffffu, sv, j);
            uint2 v = ((const uint2*)(g_h16 + (size_t)s * D))[lane];
            float2 b0 = __half22float2(*(__half2*)&v.x);
            float2 b1 = __half22float2(*(__half2*)&v.y);
            acc0 += b0.x; acc1 += b0.y; acc2 += b1.x; acc3 += b1.y;
        }
    }

    const float dd = g_dis[node];
    float4 bv = *(const float4*)(bias + lane * 4);
    float4 ov;
    ov.x = bv.x + dd * acc0;
    ov.y = bv.y + dd * acc1;
    ov.z = bv.z + dd * acc2;
    ov.w = bv.w + dd * acc3;
    *(float4*)(out + (size_t)node * D + lane * 4) = ov;
}

// ---------------------------------------------------------------------------
// Launch: 5 kernels
// ---------------------------------------------------------------------------
extern "C" void kernel_launch(void* const* d_in, const int* in_sizes, int n_in,
                              void* d_out, int out_size) {
    const float* x  = (const float*)d_in[0];
    const void*  ei = d_in[1];
    const float* W  = (const float*)d_in[2];
    const float* b  = (const float*)d_in[3];
    float*       out = (float*)d_out;

    deg_count_kernel<<<(N_EDGES + 511) / 512, 256>>>(ei);
    scan_kernel<<<1, 1024>>>();
    fill_kernel<<<(N_EDGES + 255) / 256, 256>>>(ei);

    cudaFuncSetAttribute(gemm_kernel,
                         cudaFuncAttributeMaxDynamicSharedMemorySize, SM_TOTAL);
    gemm_kernel<<<(N_NODES + 127) / 128, 256, SM_TOTAL>>>(x, W);

    agg_kernel<<<(N_NODES + 7) / 8, 256>>>(b, out);
}

// round 14
// speedup vs baseline: 1.2044x; 1.2044x over previous
#include <cuda_runtime.h>
#include <cuda_fp16.h>
#include <cstdint>

#define N_NODES 50000
#define N_EDGES 600000
#define D 128

// ---------------------------------------------------------------------------
// Scratch (__device__ globals; zero-initialized at module load)
// ---------------------------------------------------------------------------
__device__ __half g_h16[(size_t)N_NODES * D]; // h~ = fp16(h * dis[src])
__device__ float  g_dis[N_NODES];             // rsqrt(deg+1)
__device__ int    g_deg[N_NODES];             // in-degree counts (reset by gemm)
__device__ int    g_idx_is32;                 // 1 if edge_index is int32
__device__ int    g_esrc[N_EDGES];            // CSR: src ids grouped by dst
__device__ int    g_rowstart[N_NODES + 1];    // CSR row offsets
__device__ int    g_cursor[N_NODES];          // fill cursors (rebuilt per replay)

// ---------------------------------------------------------------------------
// Index dtype handling
// ---------------------------------------------------------------------------
__device__ __forceinline__ int probe_is32(const void* ei) {
    const long long* p = (const long long*)ei;
    int is32 = 0;
#pragma unroll
    for (int i = 0; i < 4; i++) {
        long long v = p[i];
        if (v < 0 || v >= N_NODES) is32 = 1;
    }
    return is32;
}
__device__ __forceinline__ int load_idx(const void* ei, long long i, int is32) {
    if (is32) return ((const int*)ei)[i];
    return (int)((const long long*)ei)[i];
}

// ---------------------------------------------------------------------------
// K1: degree count, 2 edges per thread (+ publish index dtype)
// ---------------------------------------------------------------------------
__global__ void deg_count_kernel(const void* __restrict__ ei) {
    int e0 = (blockIdx.x * blockDim.x + threadIdx.x) * 2;
    int is32 = probe_is32(ei);
    if (e0 == 0) g_idx_is32 = is32;
#pragma unroll
    for (int j = 0; j < 2; j++) {
        int e = e0 + j;
        if (e < N_EDGES) {
            int d = load_idx(ei, (long long)N_EDGES + e, is32);
            atomicAdd(&g_deg[d], 1);
        }
    }
}

// ---------------------------------------------------------------------------
// K2: fused exclusive scan (single block, 1024 threads, int4 chunks of 4096).
// ---------------------------------------------------------------------------
#define SCHUNK 4096
#define NCHUNK ((N_NODES + SCHUNK - 1) / SCHUNK)   // 13

__global__ void __launch_bounds__(1024)
scan_kernel() {
    __shared__ int ws[32];
    __shared__ int s_carry;
    const int t = threadIdx.x, lane = t & 31, w = t >> 5;
    if (t == 0) s_carry = 0;
    __syncthreads();

    for (int c = 0; c < NCHUNK; c++) {
        int i4 = c * SCHUNK + t * 4;
        int4 v = make_int4(0, 0, 0, 0);
        if (i4 < N_NODES) v = *(const int4*)(g_deg + i4);
        int tsum = v.x + v.y + v.z + v.w;

        int x = tsum;
#pragma unroll
        for (int o = 1; o < 32; o <<= 1) {
            int y = __shfl_up_sync(0xffffffffu, x, o);
            if (lane >= o) x += y;
        }
        if (lane == 31) ws[w] = x;
        __syncthreads();
        if (w == 0) {
            int z = ws[lane];
#pragma unroll
            for (int o = 1; o < 32; o <<= 1) {
                int y = __shfl_up_sync(0xffffffffu, z, o);
                if (lane >= o) z += y;
            }
            ws[lane] = z;
        }
        __syncthreads();
        int woff = (w > 0) ? ws[w - 1] : 0;
        int e0 = s_carry + woff + (x - tsum);
        if (i4 < N_NODES) {
            int4 o4;
            o4.x = e0;
            o4.y = e0 + v.x;
            o4.z = o4.y + v.y;
            o4.w = o4.z + v.z;
            *(int4*)(g_rowstart + i4) = o4;
            *(int4*)(g_cursor + i4)   = o4;
        }
        int btot = ws[31];
        __syncthreads();
        if (t == 0) s_carry += btot;
        __syncthreads();
    }
    if (t == 0) g_rowstart[N_NODES] = s_carry;   // = N_EDGES
}

// ---------------------------------------------------------------------------
// K3: bucket fill — group src ids by dst
// ---------------------------------------------------------------------------
__global__ void fill_kernel(const void* __restrict__ ei) {
    int e = blockIdx.x * blockDim.x + threadIdx.x;
    if (e < N_EDGES) {
        int is32 = g_idx_is32;
        int s = load_idx(ei, e, is32);
        int d = load_idx(ei, (long long)N_EDGES + e, is32);
        int pos = atomicAdd(&g_cursor[d], 1);
        g_esrc[pos] = s;
    }
}

// ---------------------------------------------------------------------------
// K4: fp16 single-term GEMM via mma.sync.m16n8k16.f32.f16.f16.f32.
// 2 tiles (A, B) = 70 KB smem -> 2 CTAs/SM, 16 warps (latency-bound fix).
// Scalar LDS fragment loads (proven pattern; bank = 4g+t, conflict-free).
// Stores g_h16 = fp16(h * dis[row]); finalizes g_dis; resets g_deg.
// ---------------------------------------------------------------------------
#define APAD      136
#define APADW     68
#define TILE_B    (128 * APAD * 2)   // 34816
#define SM_DIS    0
#define SM_A      512
#define SM_B      (SM_A + TILE_B)
#define SM_TOTAL  (SM_B + TILE_B)    // 70144 bytes

__device__ __forceinline__ void mma16816f(float* c, const uint32_t* a,
                                          uint32_t b0, uint32_t b1) {
    asm volatile(
        "mma.sync.aligned.m16n8k16.row.col.f32.f16.f16.f32 "
        "{%0,%1,%2,%3}, {%4,%5,%6,%7}, {%8,%9}, {%0,%1,%2,%3};"
        : "+f"(c[0]), "+f"(c[1]), "+f"(c[2]), "+f"(c[3])
        : "r"(a[0]), "r"(a[1]), "r"(a[2]), "r"(a[3]), "r"(b0), "r"(b1));
}

__global__ void __launch_bounds__(256, 2)
gemm_kernel(const float* __restrict__ x,
            const float* __restrict__ W) {
    extern __shared__ char smem[];
    float*    ep_dis = (float*)(smem + SM_DIS);
    uint32_t* As = (uint32_t*)(smem + SM_A);
    uint32_t* Bs = (uint32_t*)(smem + SM_B);

    const int tid  = threadIdx.x;
    const int wid  = tid >> 5;
    const int lane = tid & 31;
    const int row0 = blockIdx.x * 128;

    // --- Degree finalize for this block's rows ---
    if (tid < 128) {
        int gr = row0 + tid;
        float dis = 0.0f;
        if (gr < N_NODES) {
            int deg = g_deg[gr];
            dis = rsqrtf((float)(deg + 1));
            g_dis[gr] = dis;
            g_deg[gr] = 0;           // reset for next graph replay
        }
        ep_dis[tid] = dis;
    }

    // --- A tile: x[row0..row0+128) -> fp16 ---
    for (int i = tid; i < 128 * 32; i += 256) {
        int r  = i >> 5;
        int c4 = (i & 31) << 2;
        int gr = row0 + r;
        float4 v = make_float4(0.f, 0.f, 0.f, 0.f);
        if (gr < N_NODES) v = *(const float4*)(x + (size_t)gr * D + c4);
        uint32_t* dh = As + r * APADW + (c4 >> 1);
        __half2 p0 = __float22half2_rn(make_float2(v.x, v.y));
        __half2 p1 = __float22half2_rn(make_float2(v.z, v.w));
        dh[0] = *(uint32_t*)&p0;
        dh[1] = *(uint32_t*)&p1;
    }

    // --- B tile: W^T (n-major rows, k contiguous) -> fp16 ---
    for (int i = tid; i < 128 * 64; i += 256) {
        int k  = i >> 6;
        int n2 = (i & 63) << 1;
        float2 v = *(const float2*)(W + k * D + n2);
        __half* bh = (__half*)(smem + SM_B);
        bh[(n2 + 0) * APAD + k] = __float2half_rn(v.x);
        bh[(n2 + 1) * APAD + k] = __float2half_rn(v.y);
    }
    __syncthreads();

    // --- MMA mainloop (scalar LDS fragment loads) ---
    const int g = lane >> 2;
    const int t = lane & 3;
    const int wrow = wid * 16;

    float acc[16][4];
#pragma unroll
    for (int nt = 0; nt < 16; nt++)
#pragma unroll
        for (int j = 0; j < 4; j++) acc[nt][j] = 0.0f;

#pragma unroll
    for (int ks = 0; ks < 8; ks++) {
        const int kw = ks * 8 + t;
        uint32_t a[4];
        a[0] = As[(wrow + g)     * APADW + kw];
        a[1] = As[(wrow + g + 8) * APADW + kw];
        a[2] = As[(wrow + g)     * APADW + kw + 4];
        a[3] = As[(wrow + g + 8) * APADW + kw + 4];
#pragma unroll
        for (int nt = 0; nt < 16; nt++) {
            const int brow = (nt * 8 + g) * APADW + kw;
            mma16816f(acc[nt], a, Bs[brow], Bs[brow + 4]);
        }
    }

    // --- Epilogue: g_h16 = fp16(h * dis[row]) ---
    const int r0 = row0 + wrow + g;
    const int r1 = r0 + 8;
    const float d0 = ep_dis[wrow + g];
    const float d1 = ep_dis[wrow + g + 8];
    const bool ok0 = (r0 < N_NODES), ok1 = (r1 < N_NODES);
#pragma unroll
    for (int nt = 0; nt < 16; nt++) {
        const int c = nt * 8 + 2 * t;
        if (ok0) {
            float2 hv = make_float2(acc[nt][0] * d0, acc[nt][1] * d0);
            *(__half2*)(g_h16 + (size_t)r0 * D + c) = __float22half2_rn(hv);
        }
        if (ok1) {
            float2 hv = make_float2(acc[nt][2] * d1, acc[nt][3] * d1);
            *(__half2*)(g_h16 + (size_t)r1 * D + c) = __float22half2_rn(hv);
        }
    }
}

// ---------------------------------------------------------------------------
// K5: pull aggregation. One warp per dst node; lane l owns cols [4l, 4l+4).
// out[d] = b + dis[d] * (h~[d] + sum_{s in N(d)} h~[s])   -- no atomics.
// ---------------------------------------------------------------------------
__global__ void __launch_bounds__(256)
agg_kernel(const float* __restrict__ bias, float* __restrict__ out) {
    int node = blockIdx.x * 8 + (threadIdx.x >> 5);
    int lane = threadIdx.x & 31;
    if (node >= N_NODES) return;

    const int rs = g_rowstart[node];
    const int re = g_rowstart[node + 1];

    // self-loop seed
    uint2 u = ((const uint2*)(g_h16 + (size_t)node * D))[lane];
    float2 a0 = __half22float2(*(__half2*)&u.x);
    float2 a1 = __half22float2(*(__half2*)&u.y);
    float acc0 = a0.x, acc1 = a0.y, acc2 = a1.x, acc3 = a1.y;

    for (int base = rs; base < re; base += 32) {
        int n = re - base;                       // edges in this batch (<=32)
        int sv = (lane < n) ? g_esrc[base + lane] : 0;
#pragma unroll 4
        for (int j = 0; j < 32; j++) {
            if (j >= n) break;
            int s = __shfl_sync(0xffffffffu, sv, j);
            uint2 v = ((const uint2*)(g_h16 + (size_t)s * D))[lane];
            float2 b0 = __half22float2(*(__half2*)&v.x);
            float2 b1 = __half22float2(*(__half2*)&v.y);
            acc0 += b0.x; acc1 += b0.y; acc2 += b1.x; acc3 += b1.y;
        }
    }

    const float dd = g_dis[node];
    float4 bv = *(const float4*)(bias + lane * 4);
    float4 ov;
    ov.x = bv.x + dd * acc0;
    ov.y = bv.y + dd * acc1;
    ov.z = bv.z + dd * acc2;
    ov.w = bv.w + dd * acc3;
    *(float4*)(out + (size_t)node * D + lane * 4) = ov;
}

// ---------------------------------------------------------------------------
// Launch: 5 kernels
// ---------------------------------------------------------------------------
extern "C" void kernel_launch(void* const* d_in, const int* in_sizes, int n_in,
                              void* d_out, int out_size) {
    const float* x  = (const float*)d_in[0];
    const void*  ei = d_in[1];
    const float* W  = (const float*)d_in[2];
    const float* b  = (const float*)d_in[3];
    float*       out = (float*)d_out;

    deg_count_kernel<<<(N_EDGES + 511) / 512, 256>>>(ei);
    scan_kernel<<<1, 1024>>>();
    fill_kernel<<<(N_EDGES + 255) / 256, 256>>>(ei);

    cudaFuncSetAttribute(gemm_kernel,
                         cudaFuncAttributeMaxDynamicSharedMemorySize, SM_TOTAL);
    gemm_kernel<<<(N_NODES + 127) / 128, 256, SM_TOTAL>>>(x, W);

    agg_kernel<<<(N_NODES + 7) / 8, 256>>>(b, out);
}

// round 15
// speedup vs baseline: 1.2175x; 1.0108x over previous
#include <cuda_runtime.h>
#include <cuda_fp16.h>
#include <cstdint>

#define N_NODES 50000
#define N_EDGES 600000
#define D 128

// ---------------------------------------------------------------------------
// Scratch (__device__ globals; zero-initialized at module load)
// ---------------------------------------------------------------------------
__device__ __half g_h16[(size_t)N_NODES * D]; // h~ = fp16(h * dis[src])
__device__ float  g_dis[N_NODES];             // rsqrt(deg+1)
__device__ int    g_deg[N_NODES];             // in-degree counts (reset by gemm)
__device__ int    g_idx_is32;                 // 1 if edge_index is int32
__device__ int    g_esrc[N_EDGES];            // CSR: src ids grouped by dst
__device__ int    g_rowstart[N_NODES + 1];    // CSR row offsets
__device__ int    g_cursor[N_NODES];          // fill cursors (rebuilt per replay)

// ---------------------------------------------------------------------------
// Index dtype handling
// ---------------------------------------------------------------------------
__device__ __forceinline__ int probe_is32(const void* ei) {
    const long long* p = (const long long*)ei;
    int is32 = 0;
#pragma unroll
    for (int i = 0; i < 4; i++) {
        long long v = p[i];
        if (v < 0 || v >= N_NODES) is32 = 1;
    }
    return is32;
}
__device__ __forceinline__ int load_idx(const void* ei, long long i, int is32) {
    if (is32) return ((const int*)ei)[i];
    return (int)((const long long*)ei)[i];
}

// ---------------------------------------------------------------------------
// K1: degree count, 2 edges per thread (+ publish index dtype)
// ---------------------------------------------------------------------------
__global__ void deg_count_kernel(const void* __restrict__ ei) {
    int e0 = (blockIdx.x * blockDim.x + threadIdx.x) * 2;
    int is32 = probe_is32(ei);
    if (e0 == 0) g_idx_is32 = is32;
#pragma unroll
    for (int j = 0; j < 2; j++) {
        int e = e0 + j;
        if (e < N_EDGES) {
            int d = load_idx(ei, (long long)N_EDGES + e, is32);
            atomicAdd(&g_deg[d], 1);
        }
    }
}

// ---------------------------------------------------------------------------
// K2: fused exclusive scan (single block, 1024 threads, int4 chunks of 4096).
// ---------------------------------------------------------------------------
#define SCHUNK 4096
#define NCHUNK ((N_NODES + SCHUNK - 1) / SCHUNK)   // 13

__global__ void __launch_bounds__(1024)
scan_kernel() {
    __shared__ int ws[32];
    __shared__ int s_carry;
    const int t = threadIdx.x, lane = t & 31, w = t >> 5;
    if (t == 0) s_carry = 0;
    __syncthreads();

    for (int c = 0; c < NCHUNK; c++) {
        int i4 = c * SCHUNK + t * 4;
        int4 v = make_int4(0, 0, 0, 0);
        if (i4 < N_NODES) v = *(const int4*)(g_deg + i4);
        int tsum = v.x + v.y + v.z + v.w;

        int x = tsum;
#pragma unroll
        for (int o = 1; o < 32; o <<= 1) {
            int y = __shfl_up_sync(0xffffffffu, x, o);
            if (lane >= o) x += y;
        }
        if (lane == 31) ws[w] = x;
        __syncthreads();
        if (w == 0) {
            int z = ws[lane];
#pragma unroll
            for (int o = 1; o < 32; o <<= 1) {
                int y = __shfl_up_sync(0xffffffffu, z, o);
                if (lane >= o) z += y;
            }
            ws[lane] = z;
        }
        __syncthreads();
        int woff = (w > 0) ? ws[w - 1] : 0;
        int e0 = s_carry + woff + (x - tsum);
        if (i4 < N_NODES) {
            int4 o4;
            o4.x = e0;
            o4.y = e0 + v.x;
            o4.z = o4.y + v.y;
            o4.w = o4.z + v.z;
            *(int4*)(g_rowstart + i4) = o4;
            *(int4*)(g_cursor + i4)   = o4;
        }
        int btot = ws[31];
        __syncthreads();
        if (t == 0) s_carry += btot;
        __syncthreads();
    }
    if (t == 0) g_rowstart[N_NODES] = s_carry;   // = N_EDGES
}

// ---------------------------------------------------------------------------
// K3: bucket fill — group src ids by dst
// ---------------------------------------------------------------------------
__global__ void fill_kernel(const void* __restrict__ ei) {
    int e = blockIdx.x * blockDim.x + threadIdx.x;
    if (e < N_EDGES) {
        int is32 = g_idx_is32;
        int s = load_idx(ei, e, is32);
        int d = load_idx(ei, (long long)N_EDGES + e, is32);
        int pos = atomicAdd(&g_cursor[d], 1);
        g_esrc[pos] = s;
    }
}

// ---------------------------------------------------------------------------
// K4: fp16 GEMM via mma.sync.m16n8k16.f32.f16.f16.f32.
// Block = 512 threads (16 warps), tile = 128 rows x 128 cols.
// Warp w: rows [16*(w>>1), +16), cols [64*(w&1), +64)  -> 8 n-tiles,
// acc = 32 regs -> ~60 regs/thread -> 2 CTAs/SM at 512 thr = 32 warps/SM
// (fixes the measured 20.5% occupancy latency bound).
// Scalar LDS fragment loads (bank = 4g+t, conflict-free).
// ---------------------------------------------------------------------------
#define APAD      136
#define APADW     68
#define TILE_B    (128 * APAD * 2)   // 34816
#define SM_DIS    0
#define SM_A      512
#define SM_B      (SM_A + TILE_B)
#define SM_TOTAL  (SM_B + TILE_B)    // 70144 bytes

__device__ __forceinline__ void mma16816f(float* c, const uint32_t* a,
                                          uint32_t b0, uint32_t b1) {
    asm volatile(
        "mma.sync.aligned.m16n8k16.row.col.f32.f16.f16.f32 "
        "{%0,%1,%2,%3}, {%4,%5,%6,%7}, {%8,%9}, {%0,%1,%2,%3};"
        : "+f"(c[0]), "+f"(c[1]), "+f"(c[2]), "+f"(c[3])
        : "r"(a[0]), "r"(a[1]), "r"(a[2]), "r"(a[3]), "r"(b0), "r"(b1));
}

__global__ void __launch_bounds__(512, 2)
gemm_kernel(const float* __restrict__ x,
            const float* __restrict__ W) {
    extern __shared__ char smem[];
    float*    ep_dis = (float*)(smem + SM_DIS);
    uint32_t* As = (uint32_t*)(smem + SM_A);
    uint32_t* Bs = (uint32_t*)(smem + SM_B);

    const int tid  = threadIdx.x;
    const int wid  = tid >> 5;
    const int lane = tid & 31;
    const int row0 = blockIdx.x * 128;

    // --- Degree finalize for this block's rows ---
    if (tid < 128) {
        int gr = row0 + tid;
        float dis = 0.0f;
        if (gr < N_NODES) {
            int deg = g_deg[gr];
            dis = rsqrtf((float)(deg + 1));
            g_dis[gr] = dis;
            g_deg[gr] = 0;           // reset for next graph replay
        }
        ep_dis[tid] = dis;
    }

    // --- A tile: x[row0..row0+128) -> fp16 ---
    for (int i = tid; i < 128 * 32; i += 512) {
        int r  = i >> 5;
        int c4 = (i & 31) << 2;
        int gr = row0 + r;
        float4 v = make_float4(0.f, 0.f, 0.f, 0.f);
        if (gr < N_NODES) v = *(const float4*)(x + (size_t)gr * D + c4);
        uint32_t* dh = As + r * APADW + (c4 >> 1);
        __half2 p0 = __float22half2_rn(make_float2(v.x, v.y));
        __half2 p1 = __float22half2_rn(make_float2(v.z, v.w));
        dh[0] = *(uint32_t*)&p0;
        dh[1] = *(uint32_t*)&p1;
    }

    // --- B tile: W^T (n-major rows, k contiguous) -> fp16 ---
    for (int i = tid; i < 128 * 64; i += 512) {
        int k  = i >> 6;
        int n2 = (i & 63) << 1;
        float2 v = *(const float2*)(W + k * D + n2);
        __half* bh = (__half*)(smem + SM_B);
        bh[(n2 + 0) * APAD + k] = __float2half_rn(v.x);
        bh[(n2 + 1) * APAD + k] = __float2half_rn(v.y);
    }
    __syncthreads();

    // --- MMA mainloop (scalar LDS fragment loads) ---
    const int g = lane >> 2;
    const int t = lane & 3;
    const int wrow = (wid >> 1) * 16;   // row group
    const int C0   = (wid & 1) * 64;    // col half

    float acc[8][4];
#pragma unroll
    for (int nt = 0; nt < 8; nt++)
#pragma unroll
        for (int j = 0; j < 4; j++) acc[nt][j] = 0.0f;

#pragma unroll
    for (int ks = 0; ks < 8; ks++) {
        const int kw = ks * 8 + t;
        uint32_t a[4];
        a[0] = As[(wrow + g)     * APADW + kw];
        a[1] = As[(wrow + g + 8) * APADW + kw];
        a[2] = As[(wrow + g)     * APADW + kw + 4];
        a[3] = As[(wrow + g + 8) * APADW + kw + 4];
#pragma unroll
        for (int nt = 0; nt < 8; nt++) {
            const int brow = (C0 + nt * 8 + g) * APADW + kw;
            mma16816f(acc[nt], a, Bs[brow], Bs[brow + 4]);
        }
    }

    // --- Epilogue: g_h16 = fp16(h * dis[row]) ---
    const int r0 = row0 + wrow + g;
    const int r1 = r0 + 8;
    const float d0 = ep_dis[wrow + g];
    const float d1 = ep_dis[wrow + g + 8];
    const bool ok0 = (r0 < N_NODES), ok1 = (r1 < N_NODES);
#pragma unroll
    for (int nt = 0; nt < 8; nt++) {
        const int c = C0 + nt * 8 + 2 * t;
        if (ok0) {
            float2 hv = make_float2(acc[nt][0] * d0, acc[nt][1] * d0);
            *(__half2*)(g_h16 + (size_t)r0 * D + c) = __float22half2_rn(hv);
        }
        if (ok1) {
            float2 hv = make_float2(acc[nt][2] * d1, acc[nt][3] * d1);
            *(__half2*)(g_h16 + (size_t)r1 * D + c) = __float22half2_rn(hv);
        }
    }
}

// ---------------------------------------------------------------------------
// K5: pull aggregation. One warp per dst node; lane l owns cols [4l, 4l+4).
// out[d] = b + dis[d] * (h~[d] + sum_{s in N(d)} h~[s])   -- no atomics.
// ---------------------------------------------------------------------------
__global__ void __launch_bounds__(256)
agg_kernel(const float* __restrict__ bias, float* __restrict__ out) {
    int node = blockIdx.x * 8 + (threadIdx.x >> 5);
    int lane = threadIdx.x & 31;
    if (node >= N_NODES) return;

    const int rs = g_rowstart[node];
    const int re = g_rowstart[node + 1];

    // self-loop seed
    uint2 u = ((const uint2*)(g_h16 + (size_t)node * D))[lane];
    float2 a0 = __half22float2(*(__half2*)&u.x);
    float2 a1 = __half22float2(*(__half2*)&u.y);
    float acc0 = a0.x, acc1 = a0.y, acc2 = a1.x, acc3 = a1.y;

    for (int base = rs; base < re; base += 32) {
        int n = re - base;                       // edges in this batch (<=32)
        int sv = (lane < n) ? g_esrc[base + lane] : 0;
#pragma unroll 4
        for (int j = 0; j < 32; j++) {
            if (j >= n) break;
            int s = __shfl_sync(0xffffffffu, sv, j);
            uint2 v = ((const uint2*)(g_h16 + (size_t)s * D))[lane];
            float2 b0 = __half22float2(*(__half2*)&v.x);
            float2 b1 = __half22float2(*(__half2*)&v.y);
            acc0 += b0.x; acc1 += b0.y; acc2 += b1.x; acc3 += b1.y;
        }
    }

    const float dd = g_dis[node];
    float4 bv = *(const float4*)(bias + lane * 4);
    float4 ov;
    ov.x = bv.x + dd * acc0;
    ov.y = bv.y + dd * acc1;
    ov.z = bv.z + dd * acc2;
    ov.w = bv.w + dd * acc3;
    *(float4*)(out + (size_t)node * D + lane * 4) = ov;
}

// ---------------------------------------------------------------------------
// Launch: 5 kernels
// ---------------------------------------------------------------------------
extern "C" void kernel_launch(void* const* d_in, const int* in_sizes, int n_in,
                              void* d_out, int out_size) {
    const float* x  = (const float*)d_in[0];
    const void*  ei = d_in[1];
    const float* W  = (const float*)d_in[2];
    const float* b  = (const float*)d_in[3];
    float*       out = (float*)d_out;

    deg_count_kernel<<<(N_EDGES + 511) / 512, 256>>>(ei);
    scan_kernel<<<1, 1024>>>();
    fill_kernel<<<(N_EDGES + 255) / 256, 256>>>(ei);

    cudaFuncSetAttribute(gemm_kernel,
                         cudaFuncAttributeMaxDynamicSharedMemorySize, SM_TOTAL);
    gemm_kernel<<<(N_NODES + 127) / 128, 512, SM_TOTAL>>>(x, W);

    agg_kernel<<<(N_NODES + 7) / 8, 256>>>(b, out);
}

// round 16
// speedup vs baseline: 1.4204x; 1.1667x over previous
#include <cuda_runtime.h>
#include <cuda_fp16.h>
#include <cstdint>

#define N_NODES 50000
#define N_EDGES 600000
#define D 128

// ---------------------------------------------------------------------------
// Scratch (__device__ globals; zero-initialized at module load)
// ---------------------------------------------------------------------------
__device__ __half g_h16[(size_t)N_NODES * D]; // h~ = fp16(h * dis[src])
__device__ __half g_w16t[128 * 136];          // W^T fp16, padded gemm-B layout
__device__ float  g_dis[N_NODES];             // rsqrt(deg+1)
__device__ int    g_deg[N_NODES];             // in-degree counts (reset by gemm)
__device__ int    g_idx_is32;                 // 1 if edge_index is int32
__device__ int    g_esrc[N_EDGES];            // CSR: src ids grouped by dst
__device__ int    g_rowstart[N_NODES + 1];    // CSR row offsets
__device__ int    g_cursor[N_NODES];          // fill cursors (rebuilt per replay)

// ---------------------------------------------------------------------------
// Index dtype handling
// ---------------------------------------------------------------------------
__device__ __forceinline__ int probe_is32(const void* ei) {
    const long long* p = (const long long*)ei;
    int is32 = 0;
#pragma unroll
    for (int i = 0; i < 4; i++) {
        long long v = p[i];
        if (v < 0 || v >= N_NODES) is32 = 1;
    }
    return is32;
}
__device__ __forceinline__ int load_idx(const void* ei, long long i, int is32) {
    if (is32) return ((const int*)ei)[i];
    return (int)((const long long*)ei)[i];
}

// ---------------------------------------------------------------------------
// K1: degree count (2 edges/thread) + one-time W -> fp16 transpose (blocks 0-3)
// ---------------------------------------------------------------------------
__global__ void deg_count_kernel(const void* __restrict__ ei,
                                 const float* __restrict__ W) {
    int e0 = (blockIdx.x * blockDim.x + threadIdx.x) * 2;
    int is32 = probe_is32(ei);
    if (e0 == 0) g_idx_is32 = is32;
#pragma unroll
    for (int j = 0; j < 2; j++) {
        int e = e0 + j;
        if (e < N_EDGES) {
            int d = load_idx(ei, (long long)N_EDGES + e, is32);
            atomicAdd(&g_deg[d], 1);
        }
    }
    // W^T fp16 in padded B-tile layout: wt[n*136 + k]
    if (blockIdx.x < 4) {
        for (int i = blockIdx.x * 256 + threadIdx.x; i < 128 * 128; i += 1024) {
            int k = i >> 7, n = i & 127;
            g_w16t[n * 136 + k] = __float2half_rn(W[i]);   // W[k*128+n] coalesced
        }
    }
}

// ---------------------------------------------------------------------------
// K2: fused exclusive scan (single block, 1024 threads, int4 chunks of 4096).
// ---------------------------------------------------------------------------
#define SCHUNK 4096
#define NCHUNK ((N_NODES + SCHUNK - 1) / SCHUNK)   // 13

__global__ void __launch_bounds__(1024)
scan_kernel() {
    __shared__ int ws[32];
    __shared__ int s_carry;
    const int t = threadIdx.x, lane = t & 31, w = t >> 5;
    if (t == 0) s_carry = 0;
    __syncthreads();

    for (int c = 0; c < NCHUNK; c++) {
        int i4 = c * SCHUNK + t * 4;
        int4 v = make_int4(0, 0, 0, 0);
        if (i4 < N_NODES) v = *(const int4*)(g_deg + i4);
        int tsum = v.x + v.y + v.z + v.w;

        int x = tsum;
#pragma unroll
        for (int o = 1; o < 32; o <<= 1) {
            int y = __shfl_up_sync(0xffffffffu, x, o);
            if (lane >= o) x += y;
        }
        if (lane == 31) ws[w] = x;
        __syncthreads();
        if (w == 0) {
            int z = ws[lane];
#pragma unroll
            for (int o = 1; o < 32; o <<= 1) {
                int y = __shfl_up_sync(0xffffffffu, z, o);
                if (lane >= o) z += y;
            }
            ws[lane] = z;
        }
        __syncthreads();
        int woff = (w > 0) ? ws[w - 1] : 0;
        int e0 = s_carry + woff + (x - tsum);
        if (i4 < N_NODES) {
            int4 o4;
            o4.x = e0;
            o4.y = e0 + v.x;
            o4.z = o4.y + v.y;
            o4.w = o4.z + v.z;
            *(int4*)(g_rowstart + i4) = o4;
            *(int4*)(g_cursor + i4)   = o4;
        }
        int btot = ws[31];
        __syncthreads();
        if (t == 0) s_carry += btot;
        __syncthreads();
    }
    if (t == 0) g_rowstart[N_NODES] = s_carry;   // = N_EDGES
}

// ---------------------------------------------------------------------------
// K3 (fused): blocks [0, GEMM_BLOCKS) do the fp16 GEMM; the rest do CSR fill.
// Fill blocks execute in the gemm's latency bubbles / tail — no serial cost.
// Valid: scan already ran (fill needs cursors; gemm consumes+resets g_deg).
// The two paths share no state.
// ---------------------------------------------------------------------------
#define APAD      136
#define APADW     68
#define TILE_B    (128 * APAD * 2)   // 34816
#define SM_DIS    0
#define SM_A      512
#define SM_B      (SM_A + TILE_B)
#define SM_TOTAL  (SM_B + TILE_B)    // 70144 bytes
#define GEMM_BLOCKS ((N_NODES + 127) / 128)        // 391
#define FILL_BLOCKS ((N_EDGES + 1023) / 1024)      // 586 (2 edges/thread, 512 thr)

__device__ __forceinline__ void mma16816f(float* c, const uint32_t* a,
                                          uint32_t b0, uint32_t b1) {
    asm volatile(
        "mma.sync.aligned.m16n8k16.row.col.f32.f16.f16.f32 "
        "{%0,%1,%2,%3}, {%4,%5,%6,%7}, {%8,%9}, {%0,%1,%2,%3};"
        : "+f"(c[0]), "+f"(c[1]), "+f"(c[2]), "+f"(c[3])
        : "r"(a[0]), "r"(a[1]), "r"(a[2]), "r"(a[3]), "r"(b0), "r"(b1));
}

__global__ void __launch_bounds__(512, 2)
gemm_fill_kernel(const float* __restrict__ x,
                 const void* __restrict__ ei) {
    const int tid = threadIdx.x;

    // ================= FILL PATH =================
    if (blockIdx.x >= GEMM_BLOCKS) {
        int fb = blockIdx.x - GEMM_BLOCKS;
        int is32 = g_idx_is32;
        long long e0 = ((long long)fb * 512 + tid) * 2;
#pragma unroll
        for (int j = 0; j < 2; j++) {
            long long e = e0 + j;
            if (e < N_EDGES) {
                int s = load_idx(ei, e, is32);
                int d = load_idx(ei, (long long)N_EDGES + e, is32);
                int pos = atomicAdd(&g_cursor[d], 1);
                g_esrc[pos] = s;
            }
        }
        return;
    }

    // ================= GEMM PATH =================
    extern __shared__ char smem[];
    float*    ep_dis = (float*)(smem + SM_DIS);
    uint32_t* As = (uint32_t*)(smem + SM_A);
    uint32_t* Bs = (uint32_t*)(smem + SM_B);

    const int wid  = tid >> 5;
    const int lane = tid & 31;
    const int row0 = blockIdx.x * 128;

    // Degree finalize for this block's rows (scan already consumed g_deg)
    if (tid < 128) {
        int gr = row0 + tid;
        float dis = 0.0f;
        if (gr < N_NODES) {
            int deg = g_deg[gr];
            dis = rsqrtf((float)(deg + 1));
            g_dis[gr] = dis;
            g_deg[gr] = 0;           // reset for next graph replay
        }
        ep_dis[tid] = dis;
    }

    // A tile: x[row0..row0+128) -> fp16
    for (int i = tid; i < 128 * 32; i += 512) {
        int r  = i >> 5;
        int c4 = (i & 31) << 2;
        int gr = row0 + r;
        float4 v = make_float4(0.f, 0.f, 0.f, 0.f);
        if (gr < N_NODES) v = *(const float4*)(x + (size_t)gr * D + c4);
        uint32_t* dh = As + r * APADW + (c4 >> 1);
        __half2 p0 = __float22half2_rn(make_float2(v.x, v.y));
        __half2 p1 = __float22half2_rn(make_float2(v.z, v.w));
        dh[0] = *(uint32_t*)&p0;
        dh[1] = *(uint32_t*)&p1;
    }

    // B tile: straight 34 KB copy of precomputed fp16 W^T (no conversion,
    // no transpose, conflict-free uint4 stores)
    {
        const uint4* src = (const uint4*)g_w16t;
        uint4* dst = (uint4*)Bs;
        for (int i = tid; i < (128 * APADW) / 4; i += 512)
            dst[i] = src[i];
    }
    __syncthreads();

    // MMA mainloop (scalar LDS fragment loads; bank = 4g+t, conflict-free)
    const int g = lane >> 2;
    const int t = lane & 3;
    const int wrow = (wid >> 1) * 16;   // row group
    const int C0   = (wid & 1) * 64;    // col half

    float acc[8][4];
#pragma unroll
    for (int nt = 0; nt < 8; nt++)
#pragma unroll
        for (int j = 0; j < 4; j++) acc[nt][j] = 0.0f;

#pragma unroll
    for (int ks = 0; ks < 8; ks++) {
        const int kw = ks * 8 + t;
        uint32_t a[4];
        a[0] = As[(wrow + g)     * APADW + kw];
        a[1] = As[(wrow + g + 8) * APADW + kw];
        a[2] = As[(wrow + g)     * APADW + kw + 4];
        a[3] = As[(wrow + g + 8) * APADW + kw + 4];
#pragma unroll
        for (int nt = 0; nt < 8; nt++) {
            const int brow = (C0 + nt * 8 + g) * APADW + kw;
            mma16816f(acc[nt], a, Bs[brow], Bs[brow + 4]);
        }
    }

    // Epilogue: g_h16 = fp16(h * dis[row])
    const int r0 = row0 + wrow + g;
    const int r1 = r0 + 8;
    const float d0 = ep_dis[wrow + g];
    const float d1 = ep_dis[wrow + g + 8];
    const bool ok0 = (r0 < N_NODES), ok1 = (r1 < N_NODES);
#pragma unroll
    for (int nt = 0; nt < 8; nt++) {
        const int c = C0 + nt * 8 + 2 * t;
        if (ok0) {
            float2 hv = make_float2(acc[nt][0] * d0, acc[nt][1] * d0);
            *(__half2*)(g_h16 + (size_t)r0 * D + c) = __float22half2_rn(hv);
        }
        if (ok1) {
            float2 hv = make_float2(acc[nt][2] * d1, acc[nt][3] * d1);
            *(__half2*)(g_h16 + (size_t)r1 * D + c) = __float22half2_rn(hv);
        }
    }
}

// ---------------------------------------------------------------------------
// K4: pull aggregation. One warp per dst node; lane l owns cols [4l, 4l+4).
// out[d] = b + dis[d] * (h~[d] + sum_{s in N(d)} h~[s])   -- no atomics.
// ---------------------------------------------------------------------------
__global__ void __launch_bounds__(256)
agg_kernel(const float* __restrict__ bias, float* __restrict__ out) {
    int node = blockIdx.x * 8 + (threadIdx.x >> 5);
    int lane = threadIdx.x & 31;
    if (node >= N_NODES) return;

    const int rs = g_rowstart[node];
    const int re = g_rowstart[node + 1];

    // self-loop seed
    uint2 u = ((const uint2*)(g_h16 + (size_t)node * D))[lane];
    float2 a0 = __half22float2(*(__half2*)&u.x);
    float2 a1 = __half22float2(*(__half2*)&u.y);
    float acc0 = a0.x, acc1 = a0.y, acc2 = a1.x, acc3 = a1.y;

    for (int base = rs; base < re; base += 32) {
        int n = re - base;                       // edges in this batch (<=32)
        int sv = (lane < n) ? g_esrc[base + lane] : 0;
#pragma unroll 4
        for (int j = 0; j < 32; j++) {
            if (j >= n) break;
            int s = __shfl_sync(0xffffffffu, sv, j);
            uint2 v = ((const uint2*)(g_h16 + (size_t)s * D))[lane];
            float2 b0 = __half22float2(*(__half2*)&v.x);
            float2 b1 = __half22float2(*(__half2*)&v.y);
            acc0 += b0.x; acc1 += b0.y; acc2 += b1.x; acc3 += b1.y;
        }
    }

    const float dd = g_dis[node];
    float4 bv = *(const float4*)(bias + lane * 4);
    float4 ov;
    ov.x = bv.x + dd * acc0;
    ov.y = bv.y + dd * acc1;
    ov.z = bv.z + dd * acc2;
    ov.w = bv.w + dd * acc3;
    *(float4*)(out + (size_t)node * D + lane * 4) = ov;
}

// ---------------------------------------------------------------------------
// Launch: 4 kernels
// ---------------------------------------------------------------------------
extern "C" void kernel_launch(void* const* d_in, const int* in_sizes, int n_in,
                              void* d_out, int out_size) {
    const float* x  = (const float*)d_in[0];
    const void*  ei = d_in[1];
    const float* W  = (const float*)d_in[2];
    const float* b  = (const float*)d_in[3];
    float*       out = (float*)d_out;

    deg_count_kernel<<<(N_EDGES + 511) / 512, 256>>>(ei, W);
    scan_kernel<<<1, 1024>>>();

    cudaFuncSetAttribute(gemm_fill_kernel,
                         cudaFuncAttributeMaxDynamicSharedMemorySize, SM_TOTAL);
    gemm_fill_kernel<<<GEMM_BLOCKS + FILL_BLOCKS, 512, SM_TOTAL>>>(x, ei);

    agg_kernel<<<(N_NODES + 7) / 8, 256>>>(b, out);
}